// round 1
// baseline (speedup 1.0000x reference)
#include <cuda_runtime.h>

#define NN_MAX 50000
#define EE_MAX 400000

// ---------------- scratch (device globals; no allocs allowed) ----------------
__device__ float g_Wcomb[128 * 512];      // [k][j]: Wn | Wq@A1q | Wk@A1k | Wv
__device__ float g_bc[512];               // bn | 0 | 0 | bv
__device__ float g_Me[64 * 128];          // We@A1e
__device__ float g_c1[128];               // bq@A1q + bk@A1k + be@A1e + b1
__device__ float g_H[NN_MAX * 128];
__device__ float g_Q[NN_MAX * 128];
__device__ float g_Kf[NN_MAX * 128];
__device__ float g_V[NN_MAX * 128];
__device__ float g_Ee[EE_MAX * 128];      // 204.8 MB
__device__ float g_s[EE_MAX];
__device__ float g_pmax[512];
__device__ float g_psum[512];
__device__ float g_red[2];                // gmax, 1/gsum
__device__ float g_acc[NN_MAX * 128];

__device__ __forceinline__ float lrelu(float x) { return x > 0.f ? x : 0.2f * x; }

// ---------------- prep: fold weights ----------------
__global__ void prep_kernel(const float* __restrict__ Wn, const float* __restrict__ Wq,
                            const float* __restrict__ Wk, const float* __restrict__ Wv,
                            const float* __restrict__ We, const float* __restrict__ A1,
                            const float* __restrict__ b1, const float* __restrict__ bq,
                            const float* __restrict__ bk, const float* __restrict__ be,
                            const float* __restrict__ bn, const float* __restrict__ bv) {
    int t = blockIdx.x * 256 + threadIdx.x;
    if (t < 128 * 512) {
        int k = t >> 9, j = t & 511;
        float val;
        if (j < 128) {
            val = Wn[k * 128 + j];
        } else if (j < 256) {
            int jj = j - 128; float s = 0.f;
            #pragma unroll 8
            for (int u = 0; u < 128; u++) s += Wq[k * 128 + u] * A1[u * 128 + jj];
            val = s;
        } else if (j < 384) {
            int jj = j - 256; float s = 0.f;
            #pragma unroll 8
            for (int u = 0; u < 128; u++) s += Wk[k * 128 + u] * A1[(128 + u) * 128 + jj];
            val = s;
        } else {
            val = Wv[k * 128 + (j - 384)];
        }
        g_Wcomb[t] = val;
    } else if (t < 65536 + 64 * 128) {
        int i = t - 65536;
        int k = i >> 7, j = i & 127;
        float s = 0.f;
        #pragma unroll 8
        for (int u = 0; u < 128; u++) s += We[k * 128 + u] * A1[(256 + u) * 128 + j];
        g_Me[i] = s;
    } else if (t < 65536 + 8192 + 128) {
        int j = t - 65536 - 8192;
        float s = b1[j];
        for (int u = 0; u < 128; u++) {
            s += bq[u] * A1[u * 128 + j];
            s += bk[u] * A1[(128 + u) * 128 + j];
            s += be[u] * A1[(256 + u) * 128 + j];
        }
        g_c1[j] = s;
    } else if (t < 65536 + 8192 + 128 + 512) {
        int j = t - (65536 + 8192 + 128);
        g_bc[j] = (j < 128) ? bn[j] : (j >= 384 ? bv[j - 384] : 0.f);
    }
}

// ---------------- tiled fp32 GEMM (64x64x32) ----------------
// MODE 0: C[M,512] = A[M,128] @ g_Wcomb + g_bc, split into g_H/g_Q/g_Kf/g_V
// MODE 1: C[M,128] = A[M,64]  @ g_Me    + g_c1 -> g_Ee
template <int MODE>
__global__ void __launch_bounds__(256) gemm_kernel(const float* __restrict__ A, int M) {
    constexpr int K  = (MODE == 0) ? 128 : 64;
    constexpr int NC = (MODE == 0) ? 512 : 128;
    const float* __restrict__ B    = (MODE == 0) ? g_Wcomb : g_Me;
    const float* __restrict__ bias = (MODE == 0) ? g_bc    : g_c1;

    __shared__ float sA[64][33];
    __shared__ float sB[32][64];

    int tid = threadIdx.x;
    int rowBase = blockIdx.y * 64;
    int colBase = blockIdx.x * 64;
    int tx = tid & 15, ty = tid >> 4;

    float acc[4][4];
    #pragma unroll
    for (int i = 0; i < 4; i++)
        #pragma unroll
        for (int j = 0; j < 4; j++) acc[i][j] = 0.f;

    #pragma unroll
    for (int k0 = 0; k0 < K; k0 += 32) {
        #pragma unroll
        for (int i = 0; i < 8; i++) {
            int idx = tid + i * 256;
            int r = idx >> 5, c = idx & 31;
            int row = rowBase + r;
            sA[r][c] = (row < M) ? A[row * K + k0 + c] : 0.f;
        }
        #pragma unroll
        for (int i = 0; i < 8; i++) {
            int idx = tid + i * 256;
            int r = idx >> 6, c = idx & 63;
            sB[r][c] = B[(k0 + r) * NC + colBase + c];
        }
        __syncthreads();
        #pragma unroll
        for (int k = 0; k < 32; k++) {
            float a[4], b[4];
            #pragma unroll
            for (int i = 0; i < 4; i++) a[i] = sA[ty * 4 + i][k];
            #pragma unroll
            for (int j = 0; j < 4; j++) b[j] = sB[k][tx * 4 + j];
            #pragma unroll
            for (int i = 0; i < 4; i++)
                #pragma unroll
                for (int j = 0; j < 4; j++) acc[i][j] += a[i] * b[j];
        }
        __syncthreads();
    }

    float* C;
    if (MODE == 0) {
        int grp = colBase >> 7;
        C = (grp == 0) ? g_H : (grp == 1) ? g_Q : (grp == 2) ? g_Kf : g_V;
    } else {
        C = g_Ee;
    }
    #pragma unroll
    for (int i = 0; i < 4; i++) {
        int row = rowBase + ty * 4 + i;
        if (row < M) {
            #pragma unroll
            for (int j = 0; j < 4; j++) {
                int col = colBase + tx * 4 + j;
                C[row * 128 + (col & 127)] = acc[i][j] + bias[col];
            }
        }
    }
}

// ---------------- edge score: s[e] = mean_h lrelu(hmid @ A2 + b2) ----------------
__global__ void __launch_bounds__(256) edge_score_kernel(const int* __restrict__ EI, int E,
                                                         const float* __restrict__ A2,
                                                         const float* __restrict__ b2) {
    __shared__ float sA2[128 * 8];
    __shared__ float sb2[8];
    for (int i = threadIdx.x; i < 1024; i += 256) sA2[i] = A2[i];
    if (threadIdx.x < 8) sb2[threadIdx.x] = b2[threadIdx.x];
    __syncthreads();

    int warp = threadIdx.x >> 5, lane = threadIdx.x & 31;
    int e = blockIdx.x * 8 + warp;
    if (e >= E) return;
    int src = EI[e], tgt = EI[E + e];

    float4 q  = *reinterpret_cast<const float4*>(&g_Q[src * 128 + lane * 4]);
    float4 kk = *reinterpret_cast<const float4*>(&g_Kf[tgt * 128 + lane * 4]);
    float4 ee = *reinterpret_cast<const float4*>(&g_Ee[e * 128 + lane * 4]);
    float hm[4];
    hm[0] = lrelu(q.x + kk.x + ee.x);
    hm[1] = lrelu(q.y + kk.y + ee.y);
    hm[2] = lrelu(q.z + kk.z + ee.z);
    hm[3] = lrelu(q.w + kk.w + ee.w);

    float ssum = 0.f;
    #pragma unroll
    for (int h = 0; h < 8; h++) {
        float p = hm[0] * sA2[(lane * 4 + 0) * 8 + h]
                + hm[1] * sA2[(lane * 4 + 1) * 8 + h]
                + hm[2] * sA2[(lane * 4 + 2) * 8 + h]
                + hm[3] * sA2[(lane * 4 + 3) * 8 + h];
        #pragma unroll
        for (int off = 16; off >= 1; off >>= 1)
            p += __shfl_xor_sync(0xffffffffu, p, off);
        ssum += lrelu(p + sb2[h]);
    }
    if (lane == 0) g_s[e] = ssum * 0.125f;
}

// ---------------- global softmax over E edges: one pass + combine ----------------
__global__ void __launch_bounds__(256) softmax_part_kernel(int E) {
    float m = -3.4e38f, sum = 0.f;
    for (int i = blockIdx.x * 256 + threadIdx.x; i < E; i += gridDim.x * 256) {
        float v = g_s[i];
        if (v > m) { sum = sum * __expf(m - v) + 1.f; m = v; }
        else       { sum += __expf(v - m); }
    }
    __shared__ float sm[256], su[256];
    sm[threadIdx.x] = m; su[threadIdx.x] = sum;
    __syncthreads();
    for (int off = 128; off; off >>= 1) {
        if (threadIdx.x < off) {
            float m2 = sm[threadIdx.x + off], s2 = su[threadIdx.x + off];
            float mm = fmaxf(sm[threadIdx.x], m2);
            su[threadIdx.x] = su[threadIdx.x] * __expf(sm[threadIdx.x] - mm) + s2 * __expf(m2 - mm);
            sm[threadIdx.x] = mm;
        }
        __syncthreads();
    }
    if (threadIdx.x == 0) { g_pmax[blockIdx.x] = sm[0]; g_psum[blockIdx.x] = su[0]; }
}

__global__ void __launch_bounds__(512) softmax_final_kernel() {
    __shared__ float sm[512], su[512];
    int t = threadIdx.x;
    sm[t] = g_pmax[t]; su[t] = g_psum[t];
    __syncthreads();
    for (int off = 256; off; off >>= 1) {
        if (t < off) {
            float m2 = sm[t + off], s2 = su[t + off];
            float mm = fmaxf(sm[t], m2);
            su[t] = su[t] * __expf(sm[t] - mm) + s2 * __expf(m2 - mm);
            sm[t] = mm;
        }
        __syncthreads();
    }
    if (t == 0) { g_red[0] = sm[0]; g_red[1] = 1.0f / su[0]; }
}

// ---------------- scatter: acc[src] += w[e] * v[tgt] ----------------
__global__ void __launch_bounds__(256) scatter_kernel(const int* __restrict__ EI, int E) {
    int t = blockIdx.x * 256 + threadIdx.x;
    int e = t >> 5;
    if (e >= E) return;
    int lane = t & 31;
    float gmax = g_red[0], ginv = g_red[1];
    float w = __expf(g_s[e] - gmax) * ginv;
    int src = EI[e], tgt = EI[E + e];
    float4 v = *reinterpret_cast<const float4*>(&g_V[tgt * 128 + lane * 4]);
    float* dst = &g_acc[src * 128 + lane * 4];
    asm volatile("red.global.add.v4.f32 [%0], {%1, %2, %3, %4};"
                 :: "l"(dst), "f"(w * v.x), "f"(w * v.y), "f"(w * v.z), "f"(w * v.w)
                 : "memory");
}

// ---------------- zero accumulator ----------------
__global__ void zero_kernel(int count) {
    for (int i = blockIdx.x * 256 + threadIdx.x; i < count; i += gridDim.x * 256)
        g_acc[i] = 0.f;
}

// ---------------- layernorm epilogue ----------------
__global__ void __launch_bounds__(256) ln_kernel(const float* __restrict__ gamma,
                                                 const float* __restrict__ beta,
                                                 float* __restrict__ out, int Nn) {
    int warp = threadIdx.x >> 5, lane = threadIdx.x & 31;
    int n = blockIdx.x * 8 + warp;
    if (n >= Nn) return;
    float4 h = *reinterpret_cast<const float4*>(&g_H[n * 128 + lane * 4]);
    float4 a = *reinterpret_cast<const float4*>(&g_acc[n * 128 + lane * 4]);
    float y[4] = {h.x + a.x, h.y + a.y, h.z + a.z, h.w + a.w};
    float sum = y[0] + y[1] + y[2] + y[3];
    float sq  = y[0] * y[0] + y[1] * y[1] + y[2] * y[2] + y[3] * y[3];
    #pragma unroll
    for (int off = 16; off >= 1; off >>= 1) {
        sum += __shfl_xor_sync(0xffffffffu, sum, off);
        sq  += __shfl_xor_sync(0xffffffffu, sq, off);
    }
    float mu  = sum * (1.f / 128.f);
    float var = sq * (1.f / 128.f) - mu * mu;
    float rs = rsqrtf(var + 1e-5f);
    #pragma unroll
    for (int c = 0; c < 4; c++) {
        int j = lane * 4 + c;
        out[n * 128 + j] = gamma[j] * (y[c] - mu) * rs + beta[j];
    }
}

// ---------------- launch ----------------
extern "C" void kernel_launch(void* const* d_in, const int* in_sizes, int n_in,
                              void* d_out, int out_size) {
    const float* node_features = (const float*)d_in[0];
    const float* edge_features = (const float*)d_in[1];
    const float* Wn = (const float*)d_in[2];
    const float* bn = (const float*)d_in[3];
    const float* Wq = (const float*)d_in[4];
    const float* bq = (const float*)d_in[5];
    const float* Wk = (const float*)d_in[6];
    const float* bk = (const float*)d_in[7];
    const float* Wv = (const float*)d_in[8];
    const float* bv = (const float*)d_in[9];
    const float* We = (const float*)d_in[10];
    const float* be = (const float*)d_in[11];
    const float* A1 = (const float*)d_in[12];
    const float* b1 = (const float*)d_in[13];
    const float* A2 = (const float*)d_in[14];
    const float* b2 = (const float*)d_in[15];
    const float* gamma = (const float*)d_in[16];
    const float* beta  = (const float*)d_in[17];
    const int*   EI    = (const int*)d_in[18];
    float* out = (float*)d_out;

    int Nn = in_sizes[0] / 128;
    int E  = in_sizes[18] / 2;

    // 1. zero accumulator
    zero_kernel<<<4096, 256>>>(Nn * 128);
    // 2. fold weights
    prep_kernel<<<(65536 + 8192 + 128 + 512 + 255) / 256, 256>>>(
        Wn, Wq, Wk, Wv, We, A1, b1, bq, bk, be, bn, bv);
    // 3. node GEMM -> h, Xq, Xk, v
    gemm_kernel<0><<<dim3(8, (Nn + 63) / 64), 256>>>(node_features, Nn);
    // 4. edge GEMM -> Ee (bias c1 folded)
    gemm_kernel<1><<<dim3(2, (E + 63) / 64), 256>>>(edge_features, E);
    // 5. edge scores
    edge_score_kernel<<<(E + 7) / 8, 256>>>(EI, E, A2, b2);
    // 6-7. global softmax stats
    softmax_part_kernel<<<512, 256>>>(E);
    softmax_final_kernel<<<1, 512>>>();
    // 8. scatter-add
    scatter_kernel<<<(E * 32 + 255) / 256, 256>>>(EI, E);
    // 9. layernorm -> output
    ln_kernel<<<(Nn + 7) / 8, 256>>>(gamma, beta, out, Nn);
}

// round 3
// speedup vs baseline: 1.6019x; 1.6019x over previous
#include <cuda_runtime.h>

#define NN_MAX 50000
#define EE_MAX 400000

// ---------------- scratch (device globals; no allocs allowed) ----------------
__device__ float g_Wcomb[128 * 512];      // [k][j]: Wn | Wq@A1q | Wk@A1k | Wv
__device__ float g_bc[512];               // bn | 0 | 0 | bv
__device__ float g_Me[64 * 128];          // We@A1e
__device__ float g_c1[128];               // bq@A1q + bk@A1k + be@A1e + b1
__device__ float g_H[NN_MAX * 128];
__device__ float g_Q[NN_MAX * 128];
__device__ float g_Kf[NN_MAX * 128];
__device__ float g_V[NN_MAX * 128];
__device__ float g_s[EE_MAX];
__device__ float g_pmax[512];
__device__ float g_psum[512];
__device__ float g_red[2];                // gmax, 1/gsum
__device__ float g_acc[NN_MAX * 128];

__device__ __forceinline__ float lrelu(float x) { return x > 0.f ? x : 0.2f * x; }

// ---------------- prep: fold weights ----------------
__global__ void prep_kernel(const float* __restrict__ Wn, const float* __restrict__ Wq,
                            const float* __restrict__ Wk, const float* __restrict__ Wv,
                            const float* __restrict__ We, const float* __restrict__ A1,
                            const float* __restrict__ b1, const float* __restrict__ bq,
                            const float* __restrict__ bk, const float* __restrict__ be,
                            const float* __restrict__ bn, const float* __restrict__ bv) {
    int t = blockIdx.x * 256 + threadIdx.x;
    if (t < 128 * 512) {
        int k = t >> 9, j = t & 511;
        float val;
        if (j < 128) {
            val = Wn[k * 128 + j];
        } else if (j < 256) {
            int jj = j - 128; float s = 0.f;
            #pragma unroll 8
            for (int u = 0; u < 128; u++) s += Wq[k * 128 + u] * A1[u * 128 + jj];
            val = s;
        } else if (j < 384) {
            int jj = j - 256; float s = 0.f;
            #pragma unroll 8
            for (int u = 0; u < 128; u++) s += Wk[k * 128 + u] * A1[(128 + u) * 128 + jj];
            val = s;
        } else {
            val = Wv[k * 128 + (j - 384)];
        }
        g_Wcomb[t] = val;
    } else if (t < 65536 + 64 * 128) {
        int i = t - 65536;
        int k = i >> 7, j = i & 127;
        float s = 0.f;
        #pragma unroll 8
        for (int u = 0; u < 128; u++) s += We[k * 128 + u] * A1[(256 + u) * 128 + j];
        g_Me[i] = s;
    } else if (t < 65536 + 8192 + 128) {
        int j = t - 65536 - 8192;
        float s = b1[j];
        for (int u = 0; u < 128; u++) {
            s += bq[u] * A1[u * 128 + j];
            s += bk[u] * A1[(128 + u) * 128 + j];
            s += be[u] * A1[(256 + u) * 128 + j];
        }
        g_c1[j] = s;
    } else if (t < 65536 + 8192 + 128 + 512) {
        int j = t - (65536 + 8192 + 128);
        g_bc[j] = (j < 128) ? bn[j] : (j >= 384 ? bv[j - 384] : 0.f);
    }
}

// ---------------- node GEMM: C[M,512] = A[M,128] @ g_Wcomb + g_bc ----------------
// tile 64 rows x 128 cols, 256 threads, 4x8 outputs per thread
__global__ void __launch_bounds__(256) node_gemm_kernel(const float* __restrict__ A, int M) {
    __shared__ float sA[64 * 36];    // 64 rows x 32 k, stride 36
    __shared__ float sB[32 * 128];   // 32 k x 128 cols

    int tid = threadIdx.x;
    int tx = tid & 15, ty = tid >> 4;
    int rowBase = blockIdx.y * 64;
    int colBase = blockIdx.x * 128;

    float acc[4][8];
    #pragma unroll
    for (int i = 0; i < 4; i++)
        #pragma unroll
        for (int j = 0; j < 8; j++) acc[i][j] = 0.f;

    #pragma unroll
    for (int k0 = 0; k0 < 128; k0 += 32) {
        // sA: 64 rows x 32 floats = 512 float4 slots, 2 per thread
        #pragma unroll
        for (int i = 0; i < 2; i++) {
            int s = tid + i * 256;
            int r = s >> 3, c4 = s & 7;
            int row = rowBase + r;
            float4 v = make_float4(0.f, 0.f, 0.f, 0.f);
            if (row < M) v = *reinterpret_cast<const float4*>(&A[row * 128 + k0 + c4 * 4]);
            *reinterpret_cast<float4*>(&sA[r * 36 + c4 * 4]) = v;
        }
        // sB: 32 rows x 128 floats = 1024 float4 slots, 4 per thread
        #pragma unroll
        for (int i = 0; i < 4; i++) {
            int s = tid + i * 256;
            int r = s >> 5, c4 = s & 31;
            *reinterpret_cast<float4*>(&sB[r * 128 + c4 * 4]) =
                *reinterpret_cast<const float4*>(&g_Wcomb[(k0 + r) * 512 + colBase + c4 * 4]);
        }
        __syncthreads();
        #pragma unroll
        for (int k = 0; k < 32; k++) {
            float a[4];
            #pragma unroll
            for (int i = 0; i < 4; i++) a[i] = sA[(ty * 4 + i) * 36 + k];
            float4 b0 = *reinterpret_cast<const float4*>(&sB[k * 128 + tx * 8]);
            float4 b1 = *reinterpret_cast<const float4*>(&sB[k * 128 + tx * 8 + 4]);
            #pragma unroll
            for (int i = 0; i < 4; i++) {
                acc[i][0] += a[i] * b0.x; acc[i][1] += a[i] * b0.y;
                acc[i][2] += a[i] * b0.z; acc[i][3] += a[i] * b0.w;
                acc[i][4] += a[i] * b1.x; acc[i][5] += a[i] * b1.y;
                acc[i][6] += a[i] * b1.z; acc[i][7] += a[i] * b1.w;
            }
        }
        __syncthreads();
    }

    int grp = colBase >> 7;
    float* C = (grp == 0) ? g_H : (grp == 1) ? g_Q : (grp == 2) ? g_Kf : g_V;
    float4 bias0 = *reinterpret_cast<const float4*>(&g_bc[colBase + tx * 8]);
    float4 bias1 = *reinterpret_cast<const float4*>(&g_bc[colBase + tx * 8 + 4]);
    #pragma unroll
    for (int i = 0; i < 4; i++) {
        int row = rowBase + ty * 4 + i;
        if (row < M) {
            float4 o0 = make_float4(acc[i][0] + bias0.x, acc[i][1] + bias0.y,
                                    acc[i][2] + bias0.z, acc[i][3] + bias0.w);
            float4 o1 = make_float4(acc[i][4] + bias1.x, acc[i][5] + bias1.y,
                                    acc[i][6] + bias1.z, acc[i][7] + bias1.w);
            *reinterpret_cast<float4*>(&C[row * 128 + tx * 8])     = o0;
            *reinterpret_cast<float4*>(&C[row * 128 + tx * 8 + 4]) = o1;
        }
    }
}

// ---------------- fused edge kernel ----------------
// per block: 64 edges. GEMM tile: EF[64,64] @ Me[64,128] in registers,
// then hm = lrelu(tile + Xq[src] + Xk[tgt] + c1), heads = hm @ A2,
// shfl-reduce over the 16 column-threads -> s[e].
__global__ void __launch_bounds__(256) edge_fused_kernel(
    const float* __restrict__ EF, const int* __restrict__ EI, int E,
    const float* __restrict__ A2, const float* __restrict__ b2) {
    __shared__ float sEF[64 * 68];   // 64 edges x 64 feats, stride 68
    __shared__ float sB[32 * 128];   // Me chunk: 32 k x 128 cols
    __shared__ float sA2[1024];      // [col][h], same layout as A2
    __shared__ float sb2[8];

    int tid = threadIdx.x;
    int tx = tid & 15, ty = tid >> 4;
    int e0 = blockIdx.x * 64;

    for (int i = tid; i < 1024; i += 256) sA2[i] = A2[i];
    if (tid < 8) sb2[tid] = b2[tid];

    // load edge features: 64 rows x 64 feats = 1024 float4, 4 per thread
    #pragma unroll
    for (int i = 0; i < 4; i++) {
        int s = tid + i * 256;
        int r = s >> 4, c4 = s & 15;
        int e = e0 + r;
        float4 v = make_float4(0.f, 0.f, 0.f, 0.f);
        if (e < E) v = *reinterpret_cast<const float4*>(&EF[e * 64 + c4 * 4]);
        *reinterpret_cast<float4*>(&sEF[r * 68 + c4 * 4]) = v;
    }

    float acc[4][8];
    #pragma unroll
    for (int i = 0; i < 4; i++)
        #pragma unroll
        for (int j = 0; j < 8; j++) acc[i][j] = 0.f;

    #pragma unroll
    for (int k0 = 0; k0 < 64; k0 += 32) {
        #pragma unroll
        for (int i = 0; i < 4; i++) {
            int s = tid + i * 256;
            int r = s >> 5, c4 = s & 31;
            *reinterpret_cast<float4*>(&sB[r * 128 + c4 * 4]) =
                *reinterpret_cast<const float4*>(&g_Me[(k0 + r) * 128 + c4 * 4]);
        }
        __syncthreads();
        #pragma unroll
        for (int k = 0; k < 32; k++) {
            float a[4];
            #pragma unroll
            for (int i = 0; i < 4; i++) a[i] = sEF[(ty * 4 + i) * 68 + k0 + k];
            float4 b0 = *reinterpret_cast<const float4*>(&sB[k * 128 + tx * 8]);
            float4 b1 = *reinterpret_cast<const float4*>(&sB[k * 128 + tx * 8 + 4]);
            #pragma unroll
            for (int i = 0; i < 4; i++) {
                acc[i][0] += a[i] * b0.x; acc[i][1] += a[i] * b0.y;
                acc[i][2] += a[i] * b0.z; acc[i][3] += a[i] * b0.w;
                acc[i][4] += a[i] * b1.x; acc[i][5] += a[i] * b1.y;
                acc[i][6] += a[i] * b1.z; acc[i][7] += a[i] * b1.w;
            }
        }
        __syncthreads();
    }

    // epilogue: gather Xq/Xk, lrelu, fold A2 heads, shfl-reduce over tx
    float4 c10 = *reinterpret_cast<const float4*>(&g_c1[tx * 8]);
    float4 c11 = *reinterpret_cast<const float4*>(&g_c1[tx * 8 + 4]);

    float p[4][8];
    #pragma unroll
    for (int i = 0; i < 4; i++) {
        int e = e0 + ty * 4 + i;
        int ec = (e < E) ? e : (E - 1);
        int src = EI[ec], tgt = EI[E + ec];
        float4 q0 = *reinterpret_cast<const float4*>(&g_Q[src * 128 + tx * 8]);
        float4 q1 = *reinterpret_cast<const float4*>(&g_Q[src * 128 + tx * 8 + 4]);
        float4 k0v = *reinterpret_cast<const float4*>(&g_Kf[tgt * 128 + tx * 8]);
        float4 k1v = *reinterpret_cast<const float4*>(&g_Kf[tgt * 128 + tx * 8 + 4]);
        float hm[8];
        hm[0] = lrelu(acc[i][0] + q0.x + k0v.x + c10.x);
        hm[1] = lrelu(acc[i][1] + q0.y + k0v.y + c10.y);
        hm[2] = lrelu(acc[i][2] + q0.z + k0v.z + c10.z);
        hm[3] = lrelu(acc[i][3] + q0.w + k0v.w + c10.w);
        hm[4] = lrelu(acc[i][4] + q1.x + k1v.x + c11.x);
        hm[5] = lrelu(acc[i][5] + q1.y + k1v.y + c11.y);
        hm[6] = lrelu(acc[i][6] + q1.z + k1v.z + c11.z);
        hm[7] = lrelu(acc[i][7] + q1.w + k1v.w + c11.w);
        #pragma unroll
        for (int h = 0; h < 8; h++) {
            float s = 0.f;
            #pragma unroll
            for (int jj = 0; jj < 8; jj++) s += hm[jj] * sA2[(tx * 8 + jj) * 8 + h];
            p[i][h] = s;
        }
    }
    #pragma unroll
    for (int off = 1; off < 16; off <<= 1) {
        #pragma unroll
        for (int i = 0; i < 4; i++)
            #pragma unroll
            for (int h = 0; h < 8; h++)
                p[i][h] += __shfl_xor_sync(0xffffffffu, p[i][h], off);
    }
    if (tx == 0) {
        #pragma unroll
        for (int i = 0; i < 4; i++) {
            int e = e0 + ty * 4 + i;
            if (e < E) {
                float ssum = 0.f;
                #pragma unroll
                for (int h = 0; h < 8; h++) ssum += lrelu(p[i][h] + sb2[h]);
                g_s[e] = ssum * 0.125f;
            }
        }
    }
}

// ---------------- global softmax over E edges: one pass + combine ----------------
__global__ void __launch_bounds__(256) softmax_part_kernel(int E) {
    float m = -3.4e38f, sum = 0.f;
    for (int i = blockIdx.x * 256 + threadIdx.x; i < E; i += gridDim.x * 256) {
        float v = g_s[i];
        if (v > m) { sum = sum * __expf(m - v) + 1.f; m = v; }
        else       { sum += __expf(v - m); }
    }
    __shared__ float sm[256], su[256];
    sm[threadIdx.x] = m; su[threadIdx.x] = sum;
    __syncthreads();
    for (int off = 128; off; off >>= 1) {
        if (threadIdx.x < off) {
            float m2 = sm[threadIdx.x + off], s2 = su[threadIdx.x + off];
            float mm = fmaxf(sm[threadIdx.x], m2);
            su[threadIdx.x] = su[threadIdx.x] * __expf(sm[threadIdx.x] - mm) + s2 * __expf(m2 - mm);
            sm[threadIdx.x] = mm;
        }
        __syncthreads();
    }
    if (threadIdx.x == 0) { g_pmax[blockIdx.x] = sm[0]; g_psum[blockIdx.x] = su[0]; }
}

__global__ void __launch_bounds__(512) softmax_final_kernel() {
    __shared__ float sm[512], su[512];
    int t = threadIdx.x;
    sm[t] = g_pmax[t]; su[t] = g_psum[t];
    __syncthreads();
    for (int off = 256; off; off >>= 1) {
        if (t < off) {
            float m2 = sm[t + off], s2 = su[t + off];
            float mm = fmaxf(sm[t], m2);
            su[t] = su[t] * __expf(sm[t] - mm) + s2 * __expf(m2 - mm);
            sm[t] = mm;
        }
        __syncthreads();
    }
    if (t == 0) { g_red[0] = sm[0]; g_red[1] = 1.0f / su[0]; }
}

// ---------------- scatter: acc[src] += w[e] * v[tgt] ----------------
__global__ void __launch_bounds__(256) scatter_kernel(const int* __restrict__ EI, int E) {
    int t = blockIdx.x * 256 + threadIdx.x;
    int e = t >> 5;
    if (e >= E) return;
    int lane = t & 31;
    float gmax = g_red[0], ginv = g_red[1];
    float w = __expf(g_s[e] - gmax) * ginv;
    int src = EI[e], tgt = EI[E + e];
    float4 v = *reinterpret_cast<const float4*>(&g_V[tgt * 128 + lane * 4]);
    float* dst = &g_acc[src * 128 + lane * 4];
    asm volatile("red.global.add.v4.f32 [%0], {%1, %2, %3, %4};"
                 :: "l"(dst), "f"(w * v.x), "f"(w * v.y), "f"(w * v.z), "f"(w * v.w)
                 : "memory");
}

// ---------------- zero accumulator ----------------
__global__ void zero_kernel(int count) {
    for (int i = blockIdx.x * 256 + threadIdx.x; i < count; i += gridDim.x * 256)
        g_acc[i] = 0.f;
}

// ---------------- layernorm epilogue ----------------
__global__ void __launch_bounds__(256) ln_kernel(const float* __restrict__ gamma,
                                                 const float* __restrict__ beta,
                                                 float* __restrict__ out, int Nn) {
    int warp = threadIdx.x >> 5, lane = threadIdx.x & 31;
    int n = blockIdx.x * 8 + warp;
    if (n >= Nn) return;
    float4 h = *reinterpret_cast<const float4*>(&g_H[n * 128 + lane * 4]);
    float4 a = *reinterpret_cast<const float4*>(&g_acc[n * 128 + lane * 4]);
    float y[4] = {h.x + a.x, h.y + a.y, h.z + a.z, h.w + a.w};
    float sum = y[0] + y[1] + y[2] + y[3];
    float sq  = y[0] * y[0] + y[1] * y[1] + y[2] * y[2] + y[3] * y[3];
    #pragma unroll
    for (int off = 16; off >= 1; off >>= 1) {
        sum += __shfl_xor_sync(0xffffffffu, sum, off);
        sq  += __shfl_xor_sync(0xffffffffu, sq, off);
    }
    float mu  = sum * (1.f / 128.f);
    float var = sq * (1.f / 128.f) - mu * mu;
    float rs = rsqrtf(var + 1e-5f);
    #pragma unroll
    for (int c = 0; c < 4; c++) {
        int j = lane * 4 + c;
        out[n * 128 + j] = gamma[j] * (y[c] - mu) * rs + beta[j];
    }
}

// ---------------- launch ----------------
extern "C" void kernel_launch(void* const* d_in, const int* in_sizes, int n_in,
                              void* d_out, int out_size) {
    const float* node_features = (const float*)d_in[0];
    const float* edge_features = (const float*)d_in[1];
    const float* Wn = (const float*)d_in[2];
    const float* bn = (const float*)d_in[3];
    const float* Wq = (const float*)d_in[4];
    const float* bq = (const float*)d_in[5];
    const float* Wk = (const float*)d_in[6];
    const float* bk = (const float*)d_in[7];
    const float* Wv = (const float*)d_in[8];
    const float* bv = (const float*)d_in[9];
    const float* We = (const float*)d_in[10];
    const float* be = (const float*)d_in[11];
    const float* A1 = (const float*)d_in[12];
    const float* b1 = (const float*)d_in[13];
    const float* A2 = (const float*)d_in[14];
    const float* b2 = (const float*)d_in[15];
    const float* gamma = (const float*)d_in[16];
    const float* beta  = (const float*)d_in[17];
    const int*   EI    = (const int*)d_in[18];
    float* out = (float*)d_out;

    int Nn = in_sizes[0] / 128;
    int E  = in_sizes[18] / 2;

    zero_kernel<<<2048, 256>>>(Nn * 128);
    prep_kernel<<<(65536 + 8192 + 128 + 512 + 255) / 256, 256>>>(
        Wn, Wq, Wk, Wv, We, A1, b1, bq, bk, be, bn, bv);
    node_gemm_kernel<<<dim3(4, (Nn + 63) / 64), 256>>>(node_features, Nn);
    edge_fused_kernel<<<(E + 63) / 64, 256>>>(edge_features, EI, E, A2, b2);
    softmax_part_kernel<<<512, 256>>>(E);
    softmax_final_kernel<<<1, 512>>>();
    scatter_kernel<<<(E * 32 + 255) / 256, 256>>>(EI, E);
    ln_kernel<<<(Nn + 7) / 8, 256>>>(gamma, beta, out, Nn);
}

// round 5
// speedup vs baseline: 2.1243x; 1.3261x over previous
#include <cuda_runtime.h>

#define NN_MAX 50000
#define EE_MAX 400000

// ---------------- scratch (device globals; no allocs allowed) ----------------
__device__ float g_Wcomb[128 * 512];      // [k][j]: Wn | Wq@A1q | Wk@A1k | Wv
__device__ float g_bc[512];               // bn | 0 | 0 | bv
__device__ float g_Me[64 * 128];          // We@A1e
__device__ float g_c1[128];               // bq@A1q + bk@A1k + be@A1e + b1
__device__ float g_H[NN_MAX * 128];
__device__ float g_Q[NN_MAX * 128];
__device__ float g_Kf[NN_MAX * 128];
__device__ float g_V[NN_MAX * 128];
__device__ float g_s[EE_MAX];
__device__ float g_pmax[512];
__device__ float g_psum[512];
__device__ float g_red[2];                // gmax, 1/gsum
__device__ float g_acc[NN_MAX * 128];

__device__ __forceinline__ float lrelu(float x) { return x > 0.f ? x : 0.2f * x; }

// ---------------- prep: fold weights ----------------
__global__ void prep_kernel(const float* __restrict__ Wn, const float* __restrict__ Wq,
                            const float* __restrict__ Wk, const float* __restrict__ Wv,
                            const float* __restrict__ We, const float* __restrict__ A1,
                            const float* __restrict__ b1, const float* __restrict__ bq,
                            const float* __restrict__ bk, const float* __restrict__ be,
                            const float* __restrict__ bn, const float* __restrict__ bv) {
    int t = blockIdx.x * 256 + threadIdx.x;
    if (t < 128 * 512) {
        int k = t >> 9, j = t & 511;
        float val;
        if (j < 128) {
            val = Wn[k * 128 + j];
        } else if (j < 256) {
            int jj = j - 128; float s = 0.f;
            #pragma unroll 8
            for (int u = 0; u < 128; u++) s += Wq[k * 128 + u] * A1[u * 128 + jj];
            val = s;
        } else if (j < 384) {
            int jj = j - 256; float s = 0.f;
            #pragma unroll 8
            for (int u = 0; u < 128; u++) s += Wk[k * 128 + u] * A1[(128 + u) * 128 + jj];
            val = s;
        } else {
            val = Wv[k * 128 + (j - 384)];
        }
        g_Wcomb[t] = val;
    } else if (t < 65536 + 64 * 128) {
        int i = t - 65536;
        int k = i >> 7, j = i & 127;
        float s = 0.f;
        #pragma unroll 8
        for (int u = 0; u < 128; u++) s += We[k * 128 + u] * A1[(256 + u) * 128 + j];
        g_Me[i] = s;
    } else if (t < 65536 + 8192 + 128) {
        int j = t - 65536 - 8192;
        float s = b1[j];
        for (int u = 0; u < 128; u++) {
            s += bq[u] * A1[u * 128 + j];
            s += bk[u] * A1[(128 + u) * 128 + j];
            s += be[u] * A1[(256 + u) * 128 + j];
        }
        g_c1[j] = s;
    } else if (t < 65536 + 8192 + 128 + 512) {
        int j = t - (65536 + 8192 + 128);
        g_bc[j] = (j < 128) ? bn[j] : (j >= 384 ? bv[j - 384] : 0.f);
    }
}

// ---------------- node GEMM: C[M,512] = A[M,128] @ g_Wcomb + g_bc ----------------
// tile 64 rows x 128 cols, 256 threads, 4x8 outputs per thread.
// column mapping per thread: {tx*4..tx*4+3} and {64+tx*4..64+tx*4+3}
// -> B reads are contiguous 256B across 16 lanes (conflict-free).
__global__ void __launch_bounds__(256) node_gemm_kernel(const float* __restrict__ A, int M) {
    __shared__ float sA[64 * 36];    // 64 rows x 32 k, stride 36
    __shared__ float sB[32 * 128];   // 32 k x 128 cols

    int tid = threadIdx.x;
    int tx = tid & 15, ty = tid >> 4;
    int rowBase = blockIdx.y * 64;
    int colBase = blockIdx.x * 128;

    float acc[4][8];
    #pragma unroll
    for (int i = 0; i < 4; i++)
        #pragma unroll
        for (int j = 0; j < 8; j++) acc[i][j] = 0.f;

    #pragma unroll
    for (int k0 = 0; k0 < 128; k0 += 32) {
        #pragma unroll
        for (int i = 0; i < 2; i++) {
            int s = tid + i * 256;
            int r = s >> 3, c4 = s & 7;
            int row = rowBase + r;
            float4 v = make_float4(0.f, 0.f, 0.f, 0.f);
            if (row < M) v = *reinterpret_cast<const float4*>(&A[row * 128 + k0 + c4 * 4]);
            *reinterpret_cast<float4*>(&sA[r * 36 + c4 * 4]) = v;
        }
        #pragma unroll
        for (int i = 0; i < 4; i++) {
            int s = tid + i * 256;
            int r = s >> 5, c4 = s & 31;
            *reinterpret_cast<float4*>(&sB[r * 128 + c4 * 4]) =
                *reinterpret_cast<const float4*>(&g_Wcomb[(k0 + r) * 512 + colBase + c4 * 4]);
        }
        __syncthreads();
        #pragma unroll
        for (int k = 0; k < 32; k++) {
            float a[4];
            #pragma unroll
            for (int i = 0; i < 4; i++) a[i] = sA[(ty * 4 + i) * 36 + k];
            float4 b0 = *reinterpret_cast<const float4*>(&sB[k * 128 + tx * 4]);
            float4 b1 = *reinterpret_cast<const float4*>(&sB[k * 128 + 64 + tx * 4]);
            #pragma unroll
            for (int i = 0; i < 4; i++) {
                acc[i][0] += a[i] * b0.x; acc[i][1] += a[i] * b0.y;
                acc[i][2] += a[i] * b0.z; acc[i][3] += a[i] * b0.w;
                acc[i][4] += a[i] * b1.x; acc[i][5] += a[i] * b1.y;
                acc[i][6] += a[i] * b1.z; acc[i][7] += a[i] * b1.w;
            }
        }
        __syncthreads();
    }

    int grp = colBase >> 7;
    float* C = (grp == 0) ? g_H : (grp == 1) ? g_Q : (grp == 2) ? g_Kf : g_V;
    float4 bias0 = *reinterpret_cast<const float4*>(&g_bc[colBase + tx * 4]);
    float4 bias1 = *reinterpret_cast<const float4*>(&g_bc[colBase + 64 + tx * 4]);
    #pragma unroll
    for (int i = 0; i < 4; i++) {
        int row = rowBase + ty * 4 + i;
        if (row < M) {
            float4 o0 = make_float4(acc[i][0] + bias0.x, acc[i][1] + bias0.y,
                                    acc[i][2] + bias0.z, acc[i][3] + bias0.w);
            float4 o1 = make_float4(acc[i][4] + bias1.x, acc[i][5] + bias1.y,
                                    acc[i][6] + bias1.z, acc[i][7] + bias1.w);
            *reinterpret_cast<float4*>(&C[row * 128 + tx * 4])      = o0;
            *reinterpret_cast<float4*>(&C[row * 128 + 64 + tx * 4]) = o1;
        }
    }
}

// ---------------- fused edge kernel ----------------
// per block: 64 edges. GEMM tile: EF[64,64] @ Me[64,128] in registers,
// then hm = lrelu(tile + Xq[src] + Xk[tgt] + c1), heads = hm @ A2,
// shfl-reduce over the 16 column-threads -> s[e].
// column mapping per thread: {tx*4..} and {64+tx*4..} (conflict-free B reads)
__global__ void __launch_bounds__(256) edge_fused_kernel(
    const float* __restrict__ EF, const int* __restrict__ EI, int E,
    const float* __restrict__ A2, const float* __restrict__ b2) {
    __shared__ float sEF[64 * 68];   // 64 edges x 64 feats, stride 68
    __shared__ float sB[32 * 128];   // Me chunk: 32 k x 128 cols
    __shared__ float sA2[1024];      // [col][h], same layout as A2
    __shared__ float sb2[8];

    int tid = threadIdx.x;
    int tx = tid & 15, ty = tid >> 4;
    int e0 = blockIdx.x * 64;

    for (int i = tid; i < 1024; i += 256) sA2[i] = A2[i];
    if (tid < 8) sb2[tid] = b2[tid];

    // load edge features: 64 rows x 64 feats = 1024 float4, 4 per thread
    #pragma unroll
    for (int i = 0; i < 4; i++) {
        int s = tid + i * 256;
        int r = s >> 4, c4 = s & 15;
        int e = e0 + r;
        float4 v = make_float4(0.f, 0.f, 0.f, 0.f);
        if (e < E) v = *reinterpret_cast<const float4*>(&EF[e * 64 + c4 * 4]);
        *reinterpret_cast<float4*>(&sEF[r * 68 + c4 * 4]) = v;
    }

    float acc[4][8];
    #pragma unroll
    for (int i = 0; i < 4; i++)
        #pragma unroll
        for (int j = 0; j < 8; j++) acc[i][j] = 0.f;

    #pragma unroll
    for (int k0 = 0; k0 < 64; k0 += 32) {
        #pragma unroll
        for (int i = 0; i < 4; i++) {
            int s = tid + i * 256;
            int r = s >> 5, c4 = s & 31;
            *reinterpret_cast<float4*>(&sB[r * 128 + c4 * 4]) =
                *reinterpret_cast<const float4*>(&g_Me[(k0 + r) * 128 + c4 * 4]);
        }
        __syncthreads();
        #pragma unroll
        for (int k = 0; k < 32; k++) {
            float a[4];
            #pragma unroll
            for (int i = 0; i < 4; i++) a[i] = sEF[(ty * 4 + i) * 68 + k0 + k];
            float4 b0 = *reinterpret_cast<const float4*>(&sB[k * 128 + tx * 4]);
            float4 b1 = *reinterpret_cast<const float4*>(&sB[k * 128 + 64 + tx * 4]);
            #pragma unroll
            for (int i = 0; i < 4; i++) {
                acc[i][0] += a[i] * b0.x; acc[i][1] += a[i] * b0.y;
                acc[i][2] += a[i] * b0.z; acc[i][3] += a[i] * b0.w;
                acc[i][4] += a[i] * b1.x; acc[i][5] += a[i] * b1.y;
                acc[i][6] += a[i] * b1.z; acc[i][7] += a[i] * b1.w;
            }
        }
        __syncthreads();
    }

    // epilogue: gather Xq/Xk, lrelu, fold A2 heads, shfl-reduce over tx
    float4 c10 = *reinterpret_cast<const float4*>(&g_c1[tx * 4]);
    float4 c11 = *reinterpret_cast<const float4*>(&g_c1[64 + tx * 4]);

    float p[4][8];
    #pragma unroll
    for (int i = 0; i < 4; i++) {
        int e = e0 + ty * 4 + i;
        int ec = (e < E) ? e : (E - 1);
        int src = EI[ec], tgt = EI[E + ec];
        float4 q0 = *reinterpret_cast<const float4*>(&g_Q[src * 128 + tx * 4]);
        float4 q1 = *reinterpret_cast<const float4*>(&g_Q[src * 128 + 64 + tx * 4]);
        float4 k0v = *reinterpret_cast<const float4*>(&g_Kf[tgt * 128 + tx * 4]);
        float4 k1v = *reinterpret_cast<const float4*>(&g_Kf[tgt * 128 + 64 + tx * 4]);
        float hm[8];
        hm[0] = lrelu(acc[i][0] + q0.x + k0v.x + c10.x);
        hm[1] = lrelu(acc[i][1] + q0.y + k0v.y + c10.y);
        hm[2] = lrelu(acc[i][2] + q0.z + k0v.z + c10.z);
        hm[3] = lrelu(acc[i][3] + q0.w + k0v.w + c10.w);
        hm[4] = lrelu(acc[i][4] + q1.x + k1v.x + c11.x);
        hm[5] = lrelu(acc[i][5] + q1.y + k1v.y + c11.y);
        hm[6] = lrelu(acc[i][6] + q1.z + k1v.z + c11.z);
        hm[7] = lrelu(acc[i][7] + q1.w + k1v.w + c11.w);
        #pragma unroll
        for (int h = 0; h < 8; h++) {
            float s = 0.f;
            #pragma unroll
            for (int jj = 0; jj < 4; jj++) {
                s += hm[jj]     * sA2[(tx * 4 + jj) * 8 + h];
                s += hm[4 + jj] * sA2[(64 + tx * 4 + jj) * 8 + h];
            }
            p[i][h] = s;
        }
    }
    #pragma unroll
    for (int off = 1; off < 16; off <<= 1) {
        #pragma unroll
        for (int i = 0; i < 4; i++)
            #pragma unroll
            for (int h = 0; h < 8; h++)
                p[i][h] += __shfl_xor_sync(0xffffffffu, p[i][h], off);
    }
    if (tx == 0) {
        #pragma unroll
        for (int i = 0; i < 4; i++) {
            int e = e0 + ty * 4 + i;
            if (e < E) {
                float ssum = 0.f;
                #pragma unroll
                for (int h = 0; h < 8; h++) ssum += lrelu(p[i][h] + sb2[h]);
                g_s[e] = ssum * 0.125f;
            }
        }
    }
}

// ---------------- global softmax over E edges: one pass + combine ----------------
__global__ void __launch_bounds__(256) softmax_part_kernel(int E) {
    float m = -3.4e38f, sum = 0.f;
    for (int i = blockIdx.x * 256 + threadIdx.x; i < E; i += gridDim.x * 256) {
        float v = g_s[i];
        if (v > m) { sum = sum * __expf(m - v) + 1.f; m = v; }
        else       { sum += __expf(v - m); }
    }
    __shared__ float sm[256], su[256];
    sm[threadIdx.x] = m; su[threadIdx.x] = sum;
    __syncthreads();
    for (int off = 128; off; off >>= 1) {
        if (threadIdx.x < off) {
            float m2 = sm[threadIdx.x + off], s2 = su[threadIdx.x + off];
            float mm = fmaxf(sm[threadIdx.x], m2);
            su[threadIdx.x] = su[threadIdx.x] * __expf(sm[threadIdx.x] - mm) + s2 * __expf(m2 - mm);
            sm[threadIdx.x] = mm;
        }
        __syncthreads();
    }
    if (threadIdx.x == 0) { g_pmax[blockIdx.x] = sm[0]; g_psum[blockIdx.x] = su[0]; }
}

__global__ void __launch_bounds__(512) softmax_final_kernel() {
    __shared__ float sm[512], su[512];
    int t = threadIdx.x;
    sm[t] = g_pmax[t]; su[t] = g_psum[t];
    __syncthreads();
    for (int off = 256; off; off >>= 1) {
        if (t < off) {
            float m2 = sm[t + off], s2 = su[t + off];
            float mm = fmaxf(sm[t], m2);
            su[t] = su[t] * __expf(sm[t] - mm) + s2 * __expf(m2 - mm);
            sm[t] = mm;
        }
        __syncthreads();
    }
    if (t == 0) { g_red[0] = sm[0]; g_red[1] = 1.0f / su[0]; }
}

// ---------------- scatter: acc[src] += w[e] * v[tgt] ----------------
__global__ void __launch_bounds__(256) scatter_kernel(const int* __restrict__ EI, int E) {
    int t = blockIdx.x * 256 + threadIdx.x;
    int e = t >> 5;
    if (e >= E) return;
    int lane = t & 31;
    float gmax = g_red[0], ginv = g_red[1];
    float w = __expf(g_s[e] - gmax) * ginv;
    int src = EI[e], tgt = EI[E + e];
    float4 v = *reinterpret_cast<const float4*>(&g_V[tgt * 128 + lane * 4]);
    float* dst = &g_acc[src * 128 + lane * 4];
    asm volatile("red.global.add.v4.f32 [%0], {%1, %2, %3, %4};"
                 :: "l"(dst), "f"(w * v.x), "f"(w * v.y), "f"(w * v.z), "f"(w * v.w)
                 : "memory");
}

// ---------------- zero accumulator ----------------
__global__ void zero_kernel(int count) {
    for (int i = blockIdx.x * 256 + threadIdx.x; i < count; i += gridDim.x * 256)
        g_acc[i] = 0.f;
}

// ---------------- layernorm epilogue ----------------
__global__ void __launch_bounds__(256) ln_kernel(const float* __restrict__ gamma,
                                                 const float* __restrict__ beta,
                                                 float* __restrict__ out, int Nn) {
    int warp = threadIdx.x >> 5, lane = threadIdx.x & 31;
    int n = blockIdx.x * 8 + warp;
    if (n >= Nn) return;
    float4 h = *reinterpret_cast<const float4*>(&g_H[n * 128 + lane * 4]);
    float4 a = *reinterpret_cast<const float4*>(&g_acc[n * 128 + lane * 4]);
    float y[4] = {h.x + a.x, h.y + a.y, h.z + a.z, h.w + a.w};
    float sum = y[0] + y[1] + y[2] + y[3];
    float sq  = y[0] * y[0] + y[1] * y[1] + y[2] * y[2] + y[3] * y[3];
    #pragma unroll
    for (int off = 16; off >= 1; off >>= 1) {
        sum += __shfl_xor_sync(0xffffffffu, sum, off);
        sq  += __shfl_xor_sync(0xffffffffu, sq, off);
    }
    float mu  = sum * (1.f / 128.f);
    float var = sq * (1.f / 128.f) - mu * mu;
    float rs = rsqrtf(var + 1e-5f);
    #pragma unroll
    for (int c = 0; c < 4; c++) {
        int j = lane * 4 + c;
        out[n * 128 + j] = gamma[j] * (y[c] - mu) * rs + beta[j];
    }
}

// ---------------- launch ----------------
extern "C" void kernel_launch(void* const* d_in, const int* in_sizes, int n_in,
                              void* d_out, int out_size) {
    const float* node_features = (const float*)d_in[0];
    const float* edge_features = (const float*)d_in[1];
    const float* Wn = (const float*)d_in[2];
    const float* bn = (const float*)d_in[3];
    const float* Wq = (const float*)d_in[4];
    const float* bq = (const float*)d_in[5];
    const float* Wk = (const float*)d_in[6];
    const float* bk = (const float*)d_in[7];
    const float* Wv = (const float*)d_in[8];
    const float* bv = (const float*)d_in[9];
    const float* We = (const float*)d_in[10];
    const float* be = (const float*)d_in[11];
    const float* A1 = (const float*)d_in[12];
    const float* b1 = (const float*)d_in[13];
    const float* A2 = (const float*)d_in[14];
    const float* b2 = (const float*)d_in[15];
    const float* gamma = (const float*)d_in[16];
    const float* beta  = (const float*)d_in[17];
    const int*   EI    = (const int*)d_in[18];
    float* out = (float*)d_out;

    int Nn = in_sizes[0] / 128;
    int E  = in_sizes[18] / 2;

    zero_kernel<<<2048, 256>>>(Nn * 128);
    prep_kernel<<<(65536 + 8192 + 128 + 512 + 255) / 256, 256>>>(
        Wn, Wq, Wk, Wv, We, A1, b1, bq, bk, be, bn, bv);
    node_gemm_kernel<<<dim3(4, (Nn + 63) / 64), 256>>>(node_features, Nn);
    edge_fused_kernel<<<(E + 63) / 64, 256>>>(edge_features, EI, E, A2, b2);
    softmax_part_kernel<<<512, 256>>>(E);
    softmax_final_kernel<<<1, 512>>>();
    scatter_kernel<<<(E * 32 + 255) / 256, 256>>>(EI, E);
    ln_kernel<<<(Nn + 7) / 8, 256>>>(gamma, beta, out, Nn);
}